// round 4
// baseline (speedup 1.0000x reference)
#include <cuda_runtime.h>
#include <cstdint>

#define NN 20000
#define NE 300000
#define HD 256

// ---------------- device scratch (no allocs allowed) ----------------
__device__ int   g_is64;
__device__ int   g_row[NE];
__device__ int   g_col[NE];
__device__ int   g_deg[NN];
__device__ int   g_off[NN + 1];
__device__ int   g_pos[NN];
__device__ int   g_src[NE];          // CSR by dst: source node per slot
__device__ float g_hA[NN * HD];
__device__ float g_hB[NN * HD];
__device__ float g_ag[NN * HD];
__device__ float g_pr[NN * HD];
__device__ float g_pc[NN * HD];

// device-side scratch-buffer selector (no host symbol addressing)
__device__ __forceinline__ float* sel(int id) {
    switch (id) {
        case 0: return g_hA;
        case 1: return g_hB;
        case 2: return g_ag;
        case 3: return g_pr;
        case 4: return g_pc;
        default: return nullptr;
    }
}

// ---------------- dtype sniffing for edge_index (int32 vs int64) ----------------
// If data is int64 with values in [0, NN), every odd 32-bit word of the first
// 64 words is 0 (little-endian). For genuine int32 node ids, P(all zero) ~ 0.
__global__ void k_detect(const int* __restrict__ ei32) {
    int allzero = 1;
    for (int i = 1; i < 64; i += 2)
        if (ei32[i] != 0) allzero = 0;
    g_is64 = allzero;
}

// ---------------- prep: edge decode + degree ----------------
__global__ void k_zero_deg() {
    int i = blockIdx.x * blockDim.x + threadIdx.x;
    if (i < NN) g_deg[i] = 0;
}

__global__ void k_prep(const void* __restrict__ ei) {
    int e = blockIdx.x * blockDim.x + threadIdx.x;
    if (e < NE) {
        int r, c;
        if (g_is64) {
            r = (int)((const long long*)ei)[e];
            c = (int)((const long long*)ei)[NE + e];
        } else {
            r = ((const int*)ei)[e];
            c = ((const int*)ei)[NE + e];
        }
        r = min(max(r, 0), NN - 1);
        c = min(max(c, 0), NN - 1);
        g_row[e] = r;
        g_col[e] = c;
        atomicAdd(&g_deg[c], 1);
    }
}

// exclusive scan of degrees, single block (N=20000, 1024 thr x 20 elems)
__global__ void k_scan() {
    __shared__ int sums[1024];
    const int CH = 20;
    int t = threadIdx.x;
    int base = t * CH;
    int loc[CH];
    int s = 0;
    for (int i = 0; i < CH; i++) {
        int idx = base + i;
        int v = (idx < NN) ? g_deg[idx] : 0;
        loc[i] = s;
        s += v;
    }
    sums[t] = s;
    __syncthreads();
    for (int off = 1; off < 1024; off <<= 1) {
        int v = (t >= off) ? sums[t - off] : 0;
        __syncthreads();
        sums[t] += v;
        __syncthreads();
    }
    int pre = (t > 0) ? sums[t - 1] : 0;
    for (int i = 0; i < CH; i++) {
        int idx = base + i;
        if (idx < NN) {
            g_off[idx] = pre + loc[i];
            g_pos[idx] = pre + loc[i];
        }
    }
    if (t == 1023) g_off[NN] = sums[1023];
}

__global__ void k_fill() {
    int e = blockIdx.x * blockDim.x + threadIdx.x;
    if (e < NE) {
        int c = g_col[e];
        int p = atomicAdd(&g_pos[c], 1);
        if (p >= 0 && p < NE) g_src[p] = g_row[e];
    }
}

// ---------------- mean aggregation (gather over CSR) ----------------
// reads from input pointer (layer 1) or scratch buffer xId; writes g_ag
__global__ void k_aggr(const float* xext, int xId, int D) {
    const float* __restrict__ x = (xId >= 0) ? sel(xId) : xext;
    int i = blockIdx.x;
    int t = threadIdx.x;
    if (t >= D) return;
    int s0 = g_off[i], s1 = g_off[i + 1];
    float acc = 0.f;
    for (int e = s0; e < s1; e++)
        acc += x[(size_t)g_src[e] * D + t];
    g_ag[(size_t)i * D + t] = acc / fmaxf((float)(s1 - s0), 1.0f);
}

// ---------------- layer 1 (K=3, trivial): writes g_hA ----------------
__global__ void k_layer1(const float* __restrict__ x,
                         const float* __restrict__ Wl, const float* __restrict__ bl,
                         const float* __restrict__ Wr) {
    int i = blockIdx.x, j = threadIdx.x;
    float a0 = g_ag[i * 3 + 0], a1 = g_ag[i * 3 + 1], a2 = g_ag[i * 3 + 2];
    float x0 = x[i * 3 + 0], x1 = x[i * 3 + 1], x2 = x[i * 3 + 2];
    float v = bl[j]
            + a0 * Wl[j] + a1 * Wl[HD + j] + a2 * Wl[2 * HD + j]
            + x0 * Wr[j] + x1 * Wr[HD + j] + x2 * Wr[2 * HD + j];
    g_hA[(size_t)i * HD + j] = fmaxf(v, 0.f);
}

// ---------------- dual-operand SGEMM: C = act(A@WA [+ B@WB] [+ bias]) ----------------
// A,B,C selected from scratch via ids; WA/WB/bias are harness pointers.
// A,B: [M,256] row-major; WA,WB: [256,256] row-major; C: [M,256]
// tile 128x128, K-chunk 8, 256 threads, 8x8 micro (split 4+4 fragments)
__global__ __launch_bounds__(256) void k_sgemm(
    int aId, const float* __restrict__ WA,
    int bId, const float* __restrict__ WB,
    const float* __restrict__ bias, int cId,
    int M, int doRelu)
{
    __shared__ float As[8][128];
    __shared__ float Ws[8][128];
    int tid  = threadIdx.x;
    int row0 = blockIdx.y * 128;
    int col0 = blockIdx.x * 128;
    int tx = tid & 15, ty = tid >> 4;

    float acc[8][8];
#pragma unroll
    for (int i = 0; i < 8; i++)
#pragma unroll
        for (int j = 0; j < 8; j++) acc[i][j] = 0.f;

    int lr = tid >> 1;             // 0..127 tile row
    int lk = (tid & 1) * 4;        // 0 or 4
    int wr = tid >> 5;             // 0..7  k row
    int wc = (tid & 31) * 4;       // 0..124 col

    for (int pass = 0; pass < 2; pass++) {
        const float* X = sel(pass ? bId : aId);
        const float* W = pass ? WB : WA;
        if (X == nullptr || W == nullptr) break;
        for (int k0 = 0; k0 < 256; k0 += 8) {
            int r = row0 + lr;
            float4 av = make_float4(0.f, 0.f, 0.f, 0.f);
            if (r < M) av = *(const float4*)(X + (size_t)r * 256 + k0 + lk);
            As[lk + 0][lr] = av.x;
            As[lk + 1][lr] = av.y;
            As[lk + 2][lr] = av.z;
            As[lk + 3][lr] = av.w;
            float4 wv = *(const float4*)(W + (size_t)(k0 + wr) * 256 + col0 + wc);
            *(float4*)(&Ws[wr][wc]) = wv;
            __syncthreads();
#pragma unroll
            for (int kk = 0; kk < 8; kk++) {
                float a[8], b[8];
                *(float4*)(a)     = *(const float4*)(&As[kk][ty * 4]);
                *(float4*)(a + 4) = *(const float4*)(&As[kk][64 + ty * 4]);
                *(float4*)(b)     = *(const float4*)(&Ws[kk][tx * 4]);
                *(float4*)(b + 4) = *(const float4*)(&Ws[kk][64 + tx * 4]);
#pragma unroll
                for (int i = 0; i < 8; i++)
#pragma unroll
                    for (int j = 0; j < 8; j++)
                        acc[i][j] += a[i] * b[j];
            }
            __syncthreads();
        }
    }

    float* C = sel(cId);
    int rIdx[8], cIdx[8];
#pragma unroll
    for (int i = 0; i < 4; i++) {
        rIdx[i] = ty * 4 + i;      rIdx[4 + i] = 64 + ty * 4 + i;
        cIdx[i] = tx * 4 + i;      cIdx[4 + i] = 64 + tx * 4 + i;
    }
#pragma unroll
    for (int i = 0; i < 8; i++) {
        int r = row0 + rIdx[i];
        if (r >= M) continue;
#pragma unroll
        for (int j = 0; j < 8; j++) {
            int c = col0 + cIdx[j];
            float v = acc[i][j] + (bias ? bias[c] : 0.f);
            if (doRelu) v = fmaxf(v, 0.f);
            C[(size_t)r * 256 + c] = v;
        }
    }
}

// ---------------- fused edge MLP ----------------
// per edge: z1[k] = relu(PR[row][k] + PC[col][k] + ea*u[k] + base[k])   (k<256)
//           z2[j] = relu(sum_k z1[k]*W2[k][j] + b2[j])                  (j<128)
//           out   = sum_j z2[j]*W3[j] + b3
// tile: 128 edges x 128 cols, K-chunk 8, 256 threads, 8x8 micro
__global__ __launch_bounds__(256) void k_edge(
    const float* __restrict__ ea, const float* __restrict__ W1,
    const float* __restrict__ b1, const float* __restrict__ W2,
    const float* __restrict__ b2, const float* __restrict__ W3,
    const float* __restrict__ b3, const float* __restrict__ td,
    float* __restrict__ out)
{
    __shared__ int   rs[128], cs[128];
    __shared__ float eas[128];
    __shared__ float us[256], bases[256];
    __shared__ float z1s[8][128];
    __shared__ float w2s[8][128];

    int tid = threadIdx.x;
    int e0  = blockIdx.x * 128;

    if (tid < 128) {
        int e = e0 + tid;
        if (e < NE) { rs[tid] = g_row[e]; cs[tid] = g_col[e]; eas[tid] = ea[e]; }
        else        { rs[tid] = 0; cs[tid] = 0; eas[tid] = 0.f; }
    }
    us[tid]    = W1[512 * 256 + tid];
    bases[tid] = td[0] * W1[513 * 256 + tid] + b1[tid];
    __syncthreads();

    int tx = tid & 15, ty = tid >> 4;
    float acc[8][8];
#pragma unroll
    for (int i = 0; i < 8; i++)
#pragma unroll
        for (int j = 0; j < 8; j++) acc[i][j] = 0.f;

    int le = tid >> 1;            // edge within tile 0..127
    int lk = (tid & 1) * 4;       // 0 or 4
    int wr = tid >> 5;            // 0..7
    int wc = (tid & 31) * 4;      // 0..124

    int r = rs[le], c = cs[le];
    float ev = eas[le];
    const float* prp = g_pr + (size_t)r * 256 + lk;
    const float* pcp = g_pc + (size_t)c * 256 + lk;

    for (int k0 = 0; k0 < 256; k0 += 8) {
        float4 p4 = *(const float4*)(prp + k0);
        float4 q4 = *(const float4*)(pcp + k0);
        int kb = k0 + lk;
        z1s[lk + 0][le] = fmaxf(p4.x + q4.x + ev * us[kb + 0] + bases[kb + 0], 0.f);
        z1s[lk + 1][le] = fmaxf(p4.y + q4.y + ev * us[kb + 1] + bases[kb + 1], 0.f);
        z1s[lk + 2][le] = fmaxf(p4.z + q4.z + ev * us[kb + 2] + bases[kb + 2], 0.f);
        z1s[lk + 3][le] = fmaxf(p4.w + q4.w + ev * us[kb + 3] + bases[kb + 3], 0.f);
        float4 wv = *(const float4*)(W2 + (size_t)(k0 + wr) * 128 + wc);
        *(float4*)(&w2s[wr][wc]) = wv;
        __syncthreads();
#pragma unroll
        for (int kk = 0; kk < 8; kk++) {
            float a[8], b[8];
            *(float4*)(a)     = *(const float4*)(&z1s[kk][ty * 4]);
            *(float4*)(a + 4) = *(const float4*)(&z1s[kk][64 + ty * 4]);
            *(float4*)(b)     = *(const float4*)(&w2s[kk][tx * 4]);
            *(float4*)(b + 4) = *(const float4*)(&w2s[kk][64 + tx * 4]);
#pragma unroll
            for (int i = 0; i < 8; i++)
#pragma unroll
                for (int j = 0; j < 8; j++)
                    acc[i][j] += a[i] * b[j];
        }
        __syncthreads();
    }

    // epilogue: relu(acc+b2) dot W3, reduce across tx (16 threads), + b3
    float b2f[8], w3f[8];
#pragma unroll
    for (int j = 0; j < 4; j++) {
        b2f[j]     = b2[tx * 4 + j];      b2f[4 + j] = b2[64 + tx * 4 + j];
        w3f[j]     = W3[tx * 4 + j];      w3f[4 + j] = W3[64 + tx * 4 + j];
    }
    float bb3 = b3[0];
#pragma unroll
    for (int i = 0; i < 8; i++) {
        float p = 0.f;
#pragma unroll
        for (int j = 0; j < 8; j++) {
            float z2 = fmaxf(acc[i][j] + b2f[j], 0.f);
            p += z2 * w3f[j];
        }
        // lane = (ty&1)*16 + tx -> xor over bits 0..3 reduces over tx
        p += __shfl_xor_sync(0xffffffffu, p, 1);
        p += __shfl_xor_sync(0xffffffffu, p, 2);
        p += __shfl_xor_sync(0xffffffffu, p, 4);
        p += __shfl_xor_sync(0xffffffffu, p, 8);
        if (tx == 0) {
            int er = (i < 4) ? (ty * 4 + i) : (64 + ty * 4 + (i - 4));
            int e = e0 + er;
            if (e < NE) out[e] = p + bb3;
        }
    }
}

// ---------------- launch ----------------
extern "C" void kernel_launch(void* const* d_in, const int* in_sizes, int n_in,
                              void* d_out, int out_size)
{
    (void)in_sizes; (void)n_in; (void)out_size;
    const float* x   = (const float*)d_in[0];
    const void*  ei  = d_in[1];
    const float* ea  = (const float*)d_in[2];
    const float* td  = (const float*)d_in[3];
    const float* Wl1 = (const float*)d_in[4];
    const float* bl1 = (const float*)d_in[5];
    const float* Wr1 = (const float*)d_in[6];
    const float* Wl2 = (const float*)d_in[7];
    const float* bl2 = (const float*)d_in[8];
    const float* Wr2 = (const float*)d_in[9];
    const float* Wl3 = (const float*)d_in[10];
    const float* bl3 = (const float*)d_in[11];
    const float* Wr3 = (const float*)d_in[12];
    const float* W1  = (const float*)d_in[13];
    const float* b1  = (const float*)d_in[14];
    const float* W2  = (const float*)d_in[15];
    const float* b2  = (const float*)d_in[16];
    const float* W3  = (const float*)d_in[17];
    const float* b3  = (const float*)d_in[18];
    float* out = (float*)d_out;

    // CSR build (with edge_index dtype sniffing)
    k_detect<<<1, 1>>>((const int*)ei);
    k_zero_deg<<<(NN + 255) / 256, 256>>>();
    k_prep<<<(NE + 255) / 256, 256>>>(ei);
    k_scan<<<1, 1024>>>();
    k_fill<<<(NE + 255) / 256, 256>>>();

    dim3 ggrid(2, (NN + 127) / 128);

    // buffer ids: 0=g_hA, 1=g_hB, 2=g_ag, 3=g_pr, 4=g_pc  (-1 = none/external)

    // layer 1 (din=3)
    k_aggr<<<NN, 32>>>(x, -1, 3);
    k_layer1<<<NN, 256>>>(x, Wl1, bl1, Wr1);

    // layer 2: hB = relu(ag@Wl2 + hA@Wr2 + bl2)
    k_aggr<<<NN, 256>>>(nullptr, 0, 256);
    k_sgemm<<<ggrid, 256>>>(2, Wl2, 0, Wr2, bl2, 1, NN, 1);

    // layer 3: hA = relu(ag@Wl3 + hB@Wr3 + bl3)
    k_aggr<<<NN, 256>>>(nullptr, 1, 256);
    k_sgemm<<<ggrid, 256>>>(2, Wl3, 1, Wr3, bl3, 0, NN, 1);

    // edge-MLP layer-1 factorization: pr = hA @ W1[0:256], pc = hA @ W1[256:512]
    k_sgemm<<<ggrid, 256>>>(0, W1,             -1, nullptr, nullptr, 3, NN, 0);
    k_sgemm<<<ggrid, 256>>>(0, W1 + 256 * 256, -1, nullptr, nullptr, 4, NN, 0);

    // fused edge MLP (layers 2+3)
    k_edge<<<(NE + 127) / 128, 256>>>(ea, W1, b1, W2, b2, W3, b3, td, out);
}

// round 5
// speedup vs baseline: 1.0918x; 1.0918x over previous
#include <cuda_runtime.h>
#include <cstdint>

#define NN 20000
#define NE 300000
#define HD 256

// ---------------- device scratch (no allocs allowed) ----------------
__device__ int   g_is64;
__device__ int   g_row[NE];
__device__ int   g_col[NE];
__device__ int   g_deg[NN];
__device__ int   g_off[NN + 1];
__device__ int   g_pos[NN];
__device__ int   g_src[NE];          // CSR by dst: source node per slot
__device__ float g_hA[NN * HD];
__device__ float g_hB[NN * HD];
__device__ float g_ag[NN * HD];
__device__ float g_pr[NN * HD];
__device__ float g_pc[NN * HD];

// device-side scratch-buffer selector (no host symbol addressing)
__device__ __forceinline__ float* sel(int id) {
    switch (id) {
        case 0: return g_hA;
        case 1: return g_hB;
        case 2: return g_ag;
        case 3: return g_pr;
        case 4: return g_pc;
        default: return nullptr;
    }
}

// ---------------- packed f32x2 helpers (FFMA2: 2x fp32 FMA per issue) ----------
__device__ __forceinline__ unsigned long long pk2(float lo, float hi) {
    unsigned long long r;
    asm("mov.b64 %0, {%1, %2};" : "=l"(r) : "f"(lo), "f"(hi));
    return r;
}
__device__ __forceinline__ void fma2(unsigned long long& d,
                                     unsigned long long a, unsigned long long b) {
    asm("fma.rn.f32x2 %0, %1, %2, %0;" : "+l"(d) : "l"(a), "l"(b));
}
__device__ __forceinline__ float2 upk2(unsigned long long v) {
    float2 f;
    asm("mov.b64 {%0, %1}, %2;" : "=f"(f.x), "=f"(f.y) : "l"(v));
    return f;
}

// ---------------- dtype sniffing for edge_index (int32 vs int64) ----------------
__global__ void k_detect(const int* __restrict__ ei32) {
    int allzero = 1;
    for (int i = 1; i < 64; i += 2)
        if (ei32[i] != 0) allzero = 0;
    g_is64 = allzero;
}

// ---------------- prep: edge decode + degree ----------------
__global__ void k_zero_deg() {
    int i = blockIdx.x * blockDim.x + threadIdx.x;
    if (i < NN) g_deg[i] = 0;
}

__global__ void k_prep(const void* __restrict__ ei) {
    int e = blockIdx.x * blockDim.x + threadIdx.x;
    if (e < NE) {
        int r, c;
        if (g_is64) {
            r = (int)((const long long*)ei)[e];
            c = (int)((const long long*)ei)[NE + e];
        } else {
            r = ((const int*)ei)[e];
            c = ((const int*)ei)[NE + e];
        }
        r = min(max(r, 0), NN - 1);
        c = min(max(c, 0), NN - 1);
        g_row[e] = r;
        g_col[e] = c;
        atomicAdd(&g_deg[c], 1);
    }
}

// exclusive scan of degrees, single block (N=20000, 1024 thr x 20 elems)
__global__ void k_scan() {
    __shared__ int sums[1024];
    const int CH = 20;
    int t = threadIdx.x;
    int base = t * CH;
    int loc[CH];
    int s = 0;
    for (int i = 0; i < CH; i++) {
        int idx = base + i;
        int v = (idx < NN) ? g_deg[idx] : 0;
        loc[i] = s;
        s += v;
    }
    sums[t] = s;
    __syncthreads();
    for (int off = 1; off < 1024; off <<= 1) {
        int v = (t >= off) ? sums[t - off] : 0;
        __syncthreads();
        sums[t] += v;
        __syncthreads();
    }
    int pre = (t > 0) ? sums[t - 1] : 0;
    for (int i = 0; i < CH; i++) {
        int idx = base + i;
        if (idx < NN) {
            g_off[idx] = pre + loc[i];
            g_pos[idx] = pre + loc[i];
        }
    }
    if (t == 1023) g_off[NN] = sums[1023];
}

__global__ void k_fill() {
    int e = blockIdx.x * blockDim.x + threadIdx.x;
    if (e < NE) {
        int c = g_col[e];
        int p = atomicAdd(&g_pos[c], 1);
        if (p >= 0 && p < NE) g_src[p] = g_row[e];
    }
}

// ---------------- mean aggregation (gather over CSR) ----------------
__global__ void k_aggr(const float* xext, int xId, int D) {
    const float* __restrict__ x = (xId >= 0) ? sel(xId) : xext;
    int i = blockIdx.x;
    int t = threadIdx.x;
    if (t >= D) return;
    int s0 = g_off[i], s1 = g_off[i + 1];
    float acc = 0.f;
    for (int e = s0; e < s1; e++)
        acc += x[(size_t)g_src[e] * D + t];
    g_ag[(size_t)i * D + t] = acc / fmaxf((float)(s1 - s0), 1.0f);
}

// ---------------- layer 1 (K=3, trivial): writes g_hA ----------------
__global__ void k_layer1(const float* __restrict__ x,
                         const float* __restrict__ Wl, const float* __restrict__ bl,
                         const float* __restrict__ Wr) {
    int i = blockIdx.x, j = threadIdx.x;
    float a0 = g_ag[i * 3 + 0], a1 = g_ag[i * 3 + 1], a2 = g_ag[i * 3 + 2];
    float x0 = x[i * 3 + 0], x1 = x[i * 3 + 1], x2 = x[i * 3 + 2];
    float v = bl[j]
            + a0 * Wl[j] + a1 * Wl[HD + j] + a2 * Wl[2 * HD + j]
            + x0 * Wr[j] + x1 * Wr[HD + j] + x2 * Wr[2 * HD + j];
    g_hA[(size_t)i * HD + j] = fmaxf(v, 0.f);
}

// ---------------- dual-operand SGEMM: C = act(A@WA [+ B@WB] [+ bias]) ----------------
// tile 128x128, K-chunk 8, 256 threads, 8x8 micro via packed f32x2 (8x4 ull accs)
__global__ __launch_bounds__(256) void k_sgemm(
    int aId, const float* __restrict__ WA,
    int bId, const float* __restrict__ WB,
    const float* __restrict__ bias, int cId,
    int M, int doRelu)
{
    __shared__ float As[8][128];
    __shared__ float Ws[8][128];
    int tid  = threadIdx.x;
    int row0 = blockIdx.y * 128;
    int col0 = blockIdx.x * 128;
    int tx = tid & 15, ty = tid >> 4;

    unsigned long long acc2[8][4];
#pragma unroll
    for (int i = 0; i < 8; i++)
#pragma unroll
        for (int j = 0; j < 4; j++) acc2[i][j] = 0ULL;

    int lr = tid >> 1;             // 0..127 tile row
    int lk = (tid & 1) * 4;        // 0 or 4
    int wr = tid >> 5;             // 0..7  k row
    int wc = (tid & 31) * 4;       // 0..124 col

    for (int pass = 0; pass < 2; pass++) {
        const float* X = sel(pass ? bId : aId);
        const float* W = pass ? WB : WA;
        if (X == nullptr || W == nullptr) break;
        for (int k0 = 0; k0 < 256; k0 += 8) {
            int r = row0 + lr;
            float4 av = make_float4(0.f, 0.f, 0.f, 0.f);
            if (r < M) av = *(const float4*)(X + (size_t)r * 256 + k0 + lk);
            As[lk + 0][lr] = av.x;
            As[lk + 1][lr] = av.y;
            As[lk + 2][lr] = av.z;
            As[lk + 3][lr] = av.w;
            float4 wv = *(const float4*)(W + (size_t)(k0 + wr) * 256 + col0 + wc);
            *(float4*)(&Ws[wr][wc]) = wv;
            __syncthreads();
#pragma unroll
            for (int kk = 0; kk < 8; kk++) {
                float a[8], b[8];
                *(float4*)(a)     = *(const float4*)(&As[kk][ty * 4]);
                *(float4*)(a + 4) = *(const float4*)(&As[kk][64 + ty * 4]);
                *(float4*)(b)     = *(const float4*)(&Ws[kk][tx * 4]);
                *(float4*)(b + 4) = *(const float4*)(&Ws[kk][64 + tx * 4]);
                unsigned long long bp[4];
                bp[0] = pk2(b[0], b[1]);
                bp[1] = pk2(b[2], b[3]);
                bp[2] = pk2(b[4], b[5]);
                bp[3] = pk2(b[6], b[7]);
#pragma unroll
                for (int i = 0; i < 8; i++) {
                    unsigned long long aa = pk2(a[i], a[i]);
                    fma2(acc2[i][0], aa, bp[0]);
                    fma2(acc2[i][1], aa, bp[1]);
                    fma2(acc2[i][2], aa, bp[2]);
                    fma2(acc2[i][3], aa, bp[3]);
                }
            }
            __syncthreads();
        }
    }

    float* C = sel(cId);
    int rIdx[8], cIdx[8];
#pragma unroll
    for (int i = 0; i < 4; i++) {
        rIdx[i] = ty * 4 + i;      rIdx[4 + i] = 64 + ty * 4 + i;
        cIdx[i] = tx * 4 + i;      cIdx[4 + i] = 64 + tx * 4 + i;
    }
#pragma unroll
    for (int i = 0; i < 8; i++) {
        int r = row0 + rIdx[i];
        if (r >= M) continue;
        float accr[8];
#pragma unroll
        for (int j = 0; j < 4; j++) {
            float2 v = upk2(acc2[i][j]);
            accr[2 * j] = v.x;
            accr[2 * j + 1] = v.y;
        }
#pragma unroll
        for (int j = 0; j < 8; j++) {
            int c = col0 + cIdx[j];
            float v = accr[j] + (bias ? bias[c] : 0.f);
            if (doRelu) v = fmaxf(v, 0.f);
            C[(size_t)r * 256 + c] = v;
        }
    }
}

// ---------------- fused edge MLP ----------------
// per edge: z1[k] = relu(PR[row][k] + PC[col][k] + ea*u[k] + base[k])   (k<256)
//           z2[j] = relu(sum_k z1[k]*W2[k][j] + b2[j])                  (j<128)
//           out   = sum_j z2[j]*W3[j] + b3
// tile: 128 edges x 128 cols, K-chunk 8, 256 threads, 8x8 micro via f32x2
__global__ __launch_bounds__(256) void k_edge(
    const float* __restrict__ ea, const float* __restrict__ W1,
    const float* __restrict__ b1, const float* __restrict__ W2,
    const float* __restrict__ b2, const float* __restrict__ W3,
    const float* __restrict__ b3, const float* __restrict__ td,
    float* __restrict__ out)
{
    __shared__ int   rs[128], cs[128];
    __shared__ float eas[128];
    __shared__ float us[256], bases[256];
    __shared__ float z1s[8][128];
    __shared__ float w2s[8][128];

    int tid = threadIdx.x;
    int e0  = blockIdx.x * 128;

    if (tid < 128) {
        int e = e0 + tid;
        if (e < NE) { rs[tid] = g_row[e]; cs[tid] = g_col[e]; eas[tid] = ea[e]; }
        else        { rs[tid] = 0; cs[tid] = 0; eas[tid] = 0.f; }
    }
    us[tid]    = W1[512 * 256 + tid];
    bases[tid] = td[0] * W1[513 * 256 + tid] + b1[tid];
    __syncthreads();

    int tx = tid & 15, ty = tid >> 4;
    unsigned long long acc2[8][4];
#pragma unroll
    for (int i = 0; i < 8; i++)
#pragma unroll
        for (int j = 0; j < 4; j++) acc2[i][j] = 0ULL;

    int le = tid >> 1;            // edge within tile 0..127
    int lk = (tid & 1) * 4;       // 0 or 4
    int wr = tid >> 5;            // 0..7
    int wc = (tid & 31) * 4;      // 0..124

    int r = rs[le], c = cs[le];
    float ev = eas[le];
    const float* prp = g_pr + (size_t)r * 256 + lk;
    const float* pcp = g_pc + (size_t)c * 256 + lk;

    for (int k0 = 0; k0 < 256; k0 += 8) {
        float4 p4 = *(const float4*)(prp + k0);
        float4 q4 = *(const float4*)(pcp + k0);
        int kb = k0 + lk;
        z1s[lk + 0][le] = fmaxf(p4.x + q4.x + ev * us[kb + 0] + bases[kb + 0], 0.f);
        z1s[lk + 1][le] = fmaxf(p4.y + q4.y + ev * us[kb + 1] + bases[kb + 1], 0.f);
        z1s[lk + 2][le] = fmaxf(p4.z + q4.z + ev * us[kb + 2] + bases[kb + 2], 0.f);
        z1s[lk + 3][le] = fmaxf(p4.w + q4.w + ev * us[kb + 3] + bases[kb + 3], 0.f);
        float4 wv = *(const float4*)(W2 + (size_t)(k0 + wr) * 128 + wc);
        *(float4*)(&w2s[wr][wc]) = wv;
        __syncthreads();
#pragma unroll
        for (int kk = 0; kk < 8; kk++) {
            float a[8], b[8];
            *(float4*)(a)     = *(const float4*)(&z1s[kk][ty * 4]);
            *(float4*)(a + 4) = *(const float4*)(&z1s[kk][64 + ty * 4]);
            *(float4*)(b)     = *(const float4*)(&w2s[kk][tx * 4]);
            *(float4*)(b + 4) = *(const float4*)(&w2s[kk][64 + tx * 4]);
            unsigned long long bp[4];
            bp[0] = pk2(b[0], b[1]);
            bp[1] = pk2(b[2], b[3]);
            bp[2] = pk2(b[4], b[5]);
            bp[3] = pk2(b[6], b[7]);
#pragma unroll
            for (int i = 0; i < 8; i++) {
                unsigned long long aa = pk2(a[i], a[i]);
                fma2(acc2[i][0], aa, bp[0]);
                fma2(acc2[i][1], aa, bp[1]);
                fma2(acc2[i][2], aa, bp[2]);
                fma2(acc2[i][3], aa, bp[3]);
            }
        }
        __syncthreads();
    }

    // epilogue: relu(acc+b2) dot W3, reduce across tx (16 threads), + b3
    float b2f[8], w3f[8];
#pragma unroll
    for (int j = 0; j < 4; j++) {
        b2f[j]     = b2[tx * 4 + j];      b2f[4 + j] = b2[64 + tx * 4 + j];
        w3f[j]     = W3[tx * 4 + j];      w3f[4 + j] = W3[64 + tx * 4 + j];
    }
    float bb3 = b3[0];
#pragma unroll
    for (int i = 0; i < 8; i++) {
        float accr[8];
#pragma unroll
        for (int j = 0; j < 4; j++) {
            float2 v = upk2(acc2[i][j]);
            accr[2 * j] = v.x;
            accr[2 * j + 1] = v.y;
        }
        float p = 0.f;
#pragma unroll
        for (int j = 0; j < 8; j++) {
            float z2 = fmaxf(accr[j] + b2f[j], 0.f);
            p += z2 * w3f[j];
        }
        // lane = (ty&1)*16 + tx -> xor over bits 0..3 reduces over tx
        p += __shfl_xor_sync(0xffffffffu, p, 1);
        p += __shfl_xor_sync(0xffffffffu, p, 2);
        p += __shfl_xor_sync(0xffffffffu, p, 4);
        p += __shfl_xor_sync(0xffffffffu, p, 8);
        if (tx == 0) {
            int er = (i < 4) ? (ty * 4 + i) : (64 + ty * 4 + (i - 4));
            int e = e0 + er;
            if (e < NE) out[e] = p + bb3;
        }
    }
}

// ---------------- launch ----------------
extern "C" void kernel_launch(void* const* d_in, const int* in_sizes, int n_in,
                              void* d_out, int out_size)
{
    (void)in_sizes; (void)n_in; (void)out_size;
    const float* x   = (const float*)d_in[0];
    const void*  ei  = d_in[1];
    const float* ea  = (const float*)d_in[2];
    const float* td  = (const float*)d_in[3];
    const float* Wl1 = (const float*)d_in[4];
    const float* bl1 = (const float*)d_in[5];
    const float* Wr1 = (const float*)d_in[6];
    const float* Wl2 = (const float*)d_in[7];
    const float* bl2 = (const float*)d_in[8];
    const float* Wr2 = (const float*)d_in[9];
    const float* Wl3 = (const float*)d_in[10];
    const float* bl3 = (const float*)d_in[11];
    const float* Wr3 = (const float*)d_in[12];
    const float* W1  = (const float*)d_in[13];
    const float* b1  = (const float*)d_in[14];
    const float* W2  = (const float*)d_in[15];
    const float* b2  = (const float*)d_in[16];
    const float* W3  = (const float*)d_in[17];
    const float* b3  = (const float*)d_in[18];
    float* out = (float*)d_out;

    // CSR build (with edge_index dtype sniffing)
    k_detect<<<1, 1>>>((const int*)ei);
    k_zero_deg<<<(NN + 255) / 256, 256>>>();
    k_prep<<<(NE + 255) / 256, 256>>>(ei);
    k_scan<<<1, 1024>>>();
    k_fill<<<(NE + 255) / 256, 256>>>();

    dim3 ggrid(2, (NN + 127) / 128);

    // buffer ids: 0=g_hA, 1=g_hB, 2=g_ag, 3=g_pr, 4=g_pc  (-1 = none/external)

    // layer 1 (din=3)
    k_aggr<<<NN, 32>>>(x, -1, 3);
    k_layer1<<<NN, 256>>>(x, Wl1, bl1, Wr1);

    // layer 2: hB = relu(ag@Wl2 + hA@Wr2 + bl2)
    k_aggr<<<NN, 256>>>(nullptr, 0, 256);
    k_sgemm<<<ggrid, 256>>>(2, Wl2, 0, Wr2, bl2, 1, NN, 1);

    // layer 3: hA = relu(ag@Wl3 + hB@Wr3 + bl3)
    k_aggr<<<NN, 256>>>(nullptr, 1, 256);
    k_sgemm<<<ggrid, 256>>>(2, Wl3, 1, Wr3, bl3, 0, NN, 1);

    // edge-MLP layer-1 factorization: pr = hA @ W1[0:256], pc = hA @ W1[256:512]
    k_sgemm<<<ggrid, 256>>>(0, W1,             -1, nullptr, nullptr, 3, NN, 0);
    k_sgemm<<<ggrid, 256>>>(0, W1 + 256 * 256, -1, nullptr, nullptr, 4, NN, 0);

    // fused edge MLP (layers 2+3)
    k_edge<<<(NE + 127) / 128, 256>>>(ea, W1, b1, W2, b2, W3, b3, td, out);
}

// round 8
// speedup vs baseline: 1.2811x; 1.1734x over previous
#include <cuda_runtime.h>
#include <cuda_bf16.h>
#include <cstdint>

#define NN 20000
#define NE 300000
#define HD 256

// ---------------- device scratch (no allocs allowed) ----------------
__device__ int   g_is64;
__device__ int   g_row[NE];
__device__ int   g_col[NE];
__device__ int   g_deg[NN];
__device__ int   g_off[NN + 1];
__device__ int   g_pos[NN];
__device__ int   g_src[NE];
__device__ float g_hA[NN * HD];
__device__ float g_hB[NN * HD];
__device__ float g_ag[NN * HD];
__device__ float g_pr[NN * HD];
__device__ float g_pc[NN * HD];
// W2^T bf16 hi/lo images, layout [j][k]: j=0..127 (out col), k=0..255
__device__ __nv_bfloat16 g_w2hi[128 * 256];
__device__ __nv_bfloat16 g_w2lo[128 * 256];

__device__ __forceinline__ float* sel(int id) {
    switch (id) {
        case 0: return g_hA;
        case 1: return g_hB;
        case 2: return g_ag;
        case 3: return g_pr;
        case 4: return g_pc;
        default: return nullptr;
    }
}

// ---------------- packed f32x2 helpers ----------
__device__ __forceinline__ unsigned long long pk2(float lo, float hi) {
    unsigned long long r;
    asm("mov.b64 %0, {%1, %2};" : "=l"(r) : "f"(lo), "f"(hi));
    return r;
}
__device__ __forceinline__ void fma2(unsigned long long& d,
                                     unsigned long long a, unsigned long long b) {
    asm("fma.rn.f32x2 %0, %1, %2, %0;" : "+l"(d) : "l"(a), "l"(b));
}
__device__ __forceinline__ float2 upk2(unsigned long long v) {
    float2 f;
    asm("mov.b64 {%0, %1}, %2;" : "=f"(f.x), "=f"(f.y) : "l"(v));
    return f;
}

// ---------------- mma.sync helpers (baseline PTX, sm_80+) ----------------
__device__ __forceinline__ uint32_t smem_u32(const void* p) {
    uint32_t a;
    asm("{ .reg .u64 t; cvta.to.shared.u64 t, %1; cvt.u32.u64 %0, t; }" : "=r"(a) : "l"(p));
    return a;
}
__device__ __forceinline__ void ldm4(uint32_t* r, uint32_t addr) {
    asm volatile("ldmatrix.sync.aligned.m8n8.x4.shared.b16 {%0,%1,%2,%3}, [%4];"
                 : "=r"(r[0]), "=r"(r[1]), "=r"(r[2]), "=r"(r[3]) : "r"(addr));
}
__device__ __forceinline__ void mma16816(float* c, const uint32_t* a,
                                         uint32_t b0, uint32_t b1) {
    asm volatile(
        "mma.sync.aligned.m16n8k16.row.col.f32.bf16.bf16.f32 "
        "{%0,%1,%2,%3},{%4,%5,%6,%7},{%8,%9},{%0,%1,%2,%3};"
        : "+f"(c[0]), "+f"(c[1]), "+f"(c[2]), "+f"(c[3])
        : "r"(a[0]), "r"(a[1]), "r"(a[2]), "r"(a[3]), "r"(b0), "r"(b1));
}
__device__ __forceinline__ uint32_t bf2pk(float a, float b) {
    __nv_bfloat162 p;
    p.x = __float2bfloat16(a);
    p.y = __float2bfloat16(b);
    return *(uint32_t*)&p;
}

// ---------------- dtype sniffing for edge_index ----------------
__global__ void k_detect(const int* __restrict__ ei32) {
    int allzero = 1;
    for (int i = 1; i < 64; i += 2)
        if (ei32[i] != 0) allzero = 0;
    g_is64 = allzero;
}

__global__ void k_zero_deg() {
    int i = blockIdx.x * blockDim.x + threadIdx.x;
    if (i < NN) g_deg[i] = 0;
}

__global__ void k_prep(const void* __restrict__ ei) {
    int e = blockIdx.x * blockDim.x + threadIdx.x;
    if (e < NE) {
        int r, c;
        if (g_is64) {
            r = (int)((const long long*)ei)[e];
            c = (int)((const long long*)ei)[NE + e];
        } else {
            r = ((const int*)ei)[e];
            c = ((const int*)ei)[NE + e];
        }
        r = min(max(r, 0), NN - 1);
        c = min(max(c, 0), NN - 1);
        g_row[e] = r;
        g_col[e] = c;
        atomicAdd(&g_deg[c], 1);
    }
}

__global__ void k_scan() {
    __shared__ int sums[1024];
    const int CH = 20;
    int t = threadIdx.x;
    int base = t * CH;
    int loc[CH];
    int s = 0;
    for (int i = 0; i < CH; i++) {
        int idx = base + i;
        int v = (idx < NN) ? g_deg[idx] : 0;
        loc[i] = s;
        s += v;
    }
    sums[t] = s;
    __syncthreads();
    for (int off = 1; off < 1024; off <<= 1) {
        int v = (t >= off) ? sums[t - off] : 0;
        __syncthreads();
        sums[t] += v;
        __syncthreads();
    }
    int pre = (t > 0) ? sums[t - 1] : 0;
    for (int i = 0; i < CH; i++) {
        int idx = base + i;
        if (idx < NN) {
            g_off[idx] = pre + loc[i];
            g_pos[idx] = pre + loc[i];
        }
    }
    if (t == 1023) g_off[NN] = sums[1023];
}

__global__ void k_fill() {
    int e = blockIdx.x * blockDim.x + threadIdx.x;
    if (e < NE) {
        int c = g_col[e];
        int p = atomicAdd(&g_pos[c], 1);
        if (p >= 0 && p < NE) g_src[p] = g_row[e];
    }
}

// ---------------- mean aggregation (gather over CSR) ----------------
__global__ void k_aggr(const float* xext, int xId, int D) {
    const float* __restrict__ x = (xId >= 0) ? sel(xId) : xext;
    int i = blockIdx.x;
    int t = threadIdx.x;
    if (t >= D) return;
    int s0 = g_off[i], s1 = g_off[i + 1];
    float acc = 0.f;
    for (int e = s0; e < s1; e++)
        acc += x[(size_t)g_src[e] * D + t];
    g_ag[(size_t)i * D + t] = acc / fmaxf((float)(s1 - s0), 1.0f);
}

// ---------------- layer 1 ----------------
__global__ void k_layer1(const float* __restrict__ x,
                         const float* __restrict__ Wl, const float* __restrict__ bl,
                         const float* __restrict__ Wr) {
    int i = blockIdx.x, j = threadIdx.x;
    float a0 = g_ag[i * 3 + 0], a1 = g_ag[i * 3 + 1], a2 = g_ag[i * 3 + 2];
    float x0 = x[i * 3 + 0], x1 = x[i * 3 + 1], x2 = x[i * 3 + 2];
    float v = bl[j]
            + a0 * Wl[j] + a1 * Wl[HD + j] + a2 * Wl[2 * HD + j]
            + x0 * Wr[j] + x1 * Wr[HD + j] + x2 * Wr[2 * HD + j];
    g_hA[(size_t)i * HD + j] = fmaxf(v, 0.f);
}

// ---------------- dual-operand SGEMM (f32x2, unchanged) ----------------
__global__ __launch_bounds__(256) void k_sgemm(
    int aId, const float* __restrict__ WA,
    int bId, const float* __restrict__ WB,
    const float* __restrict__ bias, int cId,
    int M, int doRelu)
{
    __shared__ float As[8][128];
    __shared__ float Ws[8][128];
    int tid  = threadIdx.x;
    int row0 = blockIdx.y * 128;
    int col0 = blockIdx.x * 128;
    int tx = tid & 15, ty = tid >> 4;

    unsigned long long acc2[8][4];
#pragma unroll
    for (int i = 0; i < 8; i++)
#pragma unroll
        for (int j = 0; j < 4; j++) acc2[i][j] = 0ULL;

    int lr = tid >> 1;
    int lk = (tid & 1) * 4;
    int wr = tid >> 5;
    int wc = (tid & 31) * 4;

    for (int pass = 0; pass < 2; pass++) {
        const float* X = sel(pass ? bId : aId);
        const float* W = pass ? WB : WA;
        if (X == nullptr || W == nullptr) break;
        for (int k0 = 0; k0 < 256; k0 += 8) {
            int r = row0 + lr;
            float4 av = make_float4(0.f, 0.f, 0.f, 0.f);
            if (r < M) av = *(const float4*)(X + (size_t)r * 256 + k0 + lk);
            As[lk + 0][lr] = av.x;
            As[lk + 1][lr] = av.y;
            As[lk + 2][lr] = av.z;
            As[lk + 3][lr] = av.w;
            float4 wv = *(const float4*)(W + (size_t)(k0 + wr) * 256 + col0 + wc);
            *(float4*)(&Ws[wr][wc]) = wv;
            __syncthreads();
#pragma unroll
            for (int kk = 0; kk < 8; kk++) {
                float a[8], b[8];
                *(float4*)(a)     = *(const float4*)(&As[kk][ty * 4]);
                *(float4*)(a + 4) = *(const float4*)(&As[kk][64 + ty * 4]);
                *(float4*)(b)     = *(const float4*)(&Ws[kk][tx * 4]);
                *(float4*)(b + 4) = *(const float4*)(&Ws[kk][64 + tx * 4]);
                unsigned long long bp[4];
                bp[0] = pk2(b[0], b[1]);
                bp[1] = pk2(b[2], b[3]);
                bp[2] = pk2(b[4], b[5]);
                bp[3] = pk2(b[6], b[7]);
#pragma unroll
                for (int i = 0; i < 8; i++) {
                    unsigned long long aa = pk2(a[i], a[i]);
                    fma2(acc2[i][0], aa, bp[0]);
                    fma2(acc2[i][1], aa, bp[1]);
                    fma2(acc2[i][2], aa, bp[2]);
                    fma2(acc2[i][3], aa, bp[3]);
                }
            }
            __syncthreads();
        }
    }

    float* C = sel(cId);
    int rIdx[8], cIdx[8];
#pragma unroll
    for (int i = 0; i < 4; i++) {
        rIdx[i] = ty * 4 + i;      rIdx[4 + i] = 64 + ty * 4 + i;
        cIdx[i] = tx * 4 + i;      cIdx[4 + i] = 64 + tx * 4 + i;
    }
#pragma unroll
    for (int i = 0; i < 8; i++) {
        int r = row0 + rIdx[i];
        if (r >= M) continue;
        float accr[8];
#pragma unroll
        for (int j = 0; j < 4; j++) {
            float2 v = upk2(acc2[i][j]);
            accr[2 * j] = v.x;
            accr[2 * j + 1] = v.y;
        }
#pragma unroll
        for (int j = 0; j < 8; j++) {
            int c = col0 + cIdx[j];
            float v = accr[j] + (bias ? bias[c] : 0.f);
            if (doRelu) v = fmaxf(v, 0.f);
            C[(size_t)r * 256 + c] = v;
        }
    }
}

// ---------------- W2^T bf16 hi/lo prep ----------------
__global__ void k_w2prep(const float* __restrict__ W2) {
    int idx = blockIdx.x * blockDim.x + threadIdx.x;   // 0..128*256-1
    if (idx >= 128 * 256) return;
    int j = idx >> 8;         // 0..127
    int k = idx & 255;        // 0..255
    float v = W2[k * 128 + j];
    __nv_bfloat16 hi = __float2bfloat16(v);
    __nv_bfloat16 lo = __float2bfloat16(v - __bfloat162float(hi));
    g_w2hi[j * 256 + k] = hi;
    g_w2lo[j * 256 + k] = lo;
}

// ---------------- mma.sync fused edge MLP ----------------
// block: 256 thr (8 warps), 128 edges. warp w owns edges m0=w*16.
// z1[128e][K] bf16 hi/lo built per K-chunk(64) in SMEM; W2^T hi/lo chunk in SMEM.
// D = Ahi*Bhi + Ahi*Blo + Alo*Bhi (fp32 accum); epilogue relu(D+b2)·W3 fused.
#define ZSTR 72   // padded row stride (bf16 elems): 144B, 16B-aligned, conflict-spread
__global__ __launch_bounds__(256) void k_edge_mma(
    const float* __restrict__ ea, const float* __restrict__ W1,
    const float* __restrict__ b1, const float* __restrict__ b2,
    const float* __restrict__ W3, const float* __restrict__ b3,
    const float* __restrict__ td, float* __restrict__ out)
{
    extern __shared__ __align__(16) char dyn[];
    __nv_bfloat16* z1hi = (__nv_bfloat16*)dyn;                 // [128][ZSTR]
    __nv_bfloat16* z1lo = z1hi + 128 * ZSTR;
    __nv_bfloat16* w2hi = z1lo + 128 * ZSTR;                   // [128j][ZSTR]
    __nv_bfloat16* w2lo = w2hi + 128 * ZSTR;

    __shared__ float us[256], bases[256], b2s[128], w3s[128];

    int tid  = threadIdx.x;
    int lane = tid & 31;
    int w    = tid >> 5;
    int e0   = blockIdx.x * 128;

    us[tid]    = W1[512 * 256 + tid];
    bases[tid] = td[0] * W1[513 * 256 + tid] + b1[tid];
    if (tid < 128) { b2s[tid] = b2[tid]; w3s[tid] = W3[tid]; }

    // per-thread z1-producer role: edge le, k-half kh
    int le = tid >> 1;
    int kh = (tid & 1) * 32;
    int ez = e0 + le;
    int r, c;
    float ev;
    if (ez < NE) { r = g_row[ez]; c = g_col[ez]; ev = ea[ez]; }
    else         { r = 0; c = 0; ev = 0.f; }
    const float* prp = g_pr + (size_t)r * 256;
    const float* pcp = g_pc + (size_t)c * 256;

    float acc[16][4];
#pragma unroll
    for (int i = 0; i < 16; i++)
#pragma unroll
        for (int j = 0; j < 4; j++) acc[i][j] = 0.f;

    // precompute ldmatrix smem addresses (element offsets fixed per lane)
    uint32_t z1hi_u = smem_u32(z1hi), z1lo_u = smem_u32(z1lo);
    uint32_t w2hi_u = smem_u32(w2hi), w2lo_u = smem_u32(w2lo);
    int m0 = w * 16;
    uint32_t a_row = m0 + (lane & 15);
    uint32_t a_col = (lane >> 4) * 8;                 // + ks*16
    int jo_in = (lane < 16) ? (lane & 7) : (8 + (lane & 7));
    int ko_in = ((lane >> 3) & 1) * 8;                // + ks*16

    __syncthreads();

    for (int kc = 0; kc < 4; kc++) {
        // ---- build z1 chunk (hi/lo bf16) ----
        {
            int kb = kc * 64 + kh;
#pragma unroll
            for (int q = 0; q < 8; q++) {
                float4 p4 = *(const float4*)(prp + kb + q * 4);
                float4 q4 = *(const float4*)(pcp + kb + q * 4);
                int kg = kb + q * 4;
                float z0 = fmaxf(p4.x + q4.x + ev * us[kg + 0] + bases[kg + 0], 0.f);
                float z1v = fmaxf(p4.y + q4.y + ev * us[kg + 1] + bases[kg + 1], 0.f);
                float z2 = fmaxf(p4.z + q4.z + ev * us[kg + 2] + bases[kg + 2], 0.f);
                float z3 = fmaxf(p4.w + q4.w + ev * us[kg + 3] + bases[kg + 3], 0.f);
                __nv_bfloat16 h0 = __float2bfloat16(z0), h1 = __float2bfloat16(z1v);
                __nv_bfloat16 h2 = __float2bfloat16(z2), h3 = __float2bfloat16(z3);
                uint32_t hi01 = bf2pk(z0, z1v);   // rounds again, identical to h0,h1
                uint32_t hi23 = bf2pk(z2, z3);
                uint32_t lo01 = bf2pk(z0 - __bfloat162float(h0), z1v - __bfloat162float(h1));
                uint32_t lo23 = bf2pk(z2 - __bfloat162float(h2), z3 - __bfloat162float(h3));
                int off = le * ZSTR + kh + q * 4;
                *(uint2*)(z1hi + off) = make_uint2(hi01, hi23);
                *(uint2*)(z1lo + off) = make_uint2(lo01, lo23);
            }
        }
        // ---- copy W2 chunk [128j][64k] hi/lo ----
        {
            const uint4* srch = (const uint4*)(g_w2hi) + kc * 8;  // row stride 256/8=32 uint4
            const uint4* srcl = (const uint4*)(g_w2lo) + kc * 8;
#pragma unroll
            for (int it = 0; it < 4; it++) {
                int i = tid + it * 256;          // 0..1023
                int row = i >> 3, part = i & 7;
                int doff = row * ZSTR + part * 8;
                *(uint4*)(w2hi + doff) = srch[row * 32 + part];
                *(uint4*)(w2lo + doff) = srcl[row * 32 + part];
            }
        }
        __syncthreads();

        // ---- MMA over this chunk ----
#pragma unroll
        for (int ks = 0; ks < 4; ks++) {
            uint32_t ahi[4], alo[4];
            uint32_t aoff = (a_row * ZSTR + ks * 16 + a_col) * 2;
            ldm4(ahi, z1hi_u + aoff);
            ldm4(alo, z1lo_u + aoff);
#pragma unroll
            for (int p = 0; p < 8; p++) {
                uint32_t bh[4], bl[4];
                uint32_t boff = ((p * 16 + jo_in) * ZSTR + ks * 16 + ko_in) * 2;
                ldm4(bh, w2hi_u + boff);
                ldm4(bl, w2lo_u + boff);
                mma16816(acc[p * 2],     ahi, bh[0], bh[1]);
                mma16816(acc[p * 2 + 1], ahi, bh[2], bh[3]);
                mma16816(acc[p * 2],     ahi, bl[0], bl[1]);
                mma16816(acc[p * 2 + 1], ahi, bl[2], bl[3]);
                mma16816(acc[p * 2],     alo, bh[0], bh[1]);
                mma16816(acc[p * 2 + 1], alo, bh[2], bh[3]);
            }
        }
        __syncthreads();
    }

    // ---- epilogue: out[e] = sum_j relu(D[e][j]+b2[j])*W3[j] + b3 ----
    float o0 = 0.f, o8 = 0.f;   // rows m0+lane/4 and m0+8+lane/4
#pragma unroll
    for (int nt = 0; nt < 16; nt++) {
        int j0 = nt * 8 + (lane & 3) * 2;
        float w30 = w3s[j0], w31 = w3s[j0 + 1];
        float bb0 = b2s[j0], bb1 = b2s[j0 + 1];
        o0 += fmaxf(acc[nt][0] + bb0, 0.f) * w30 + fmaxf(acc[nt][1] + bb1, 0.f) * w31;
        o8 += fmaxf(acc[nt][2] + bb0, 0.f) * w30 + fmaxf(acc[nt][3] + bb1, 0.f) * w31;
    }
    o0 += __shfl_xor_sync(0xffffffffu, o0, 1);
    o0 += __shfl_xor_sync(0xffffffffu, o0, 2);
    o8 += __shfl_xor_sync(0xffffffffu, o8, 1);
    o8 += __shfl_xor_sync(0xffffffffu, o8, 2);
    if ((lane & 3) == 0) {
        float bb3 = b3[0];
        int row = lane >> 2;
        int eo0 = e0 + m0 + row;
        int eo8 = e0 + m0 + 8 + row;
        if (eo0 < NE) out[eo0] = o0 + bb3;
        if (eo8 < NE) out[eo8] = o8 + bb3;
    }
}

// ---------------- launch ----------------
extern "C" void kernel_launch(void* const* d_in, const int* in_sizes, int n_in,
                              void* d_out, int out_size)
{
    (void)in_sizes; (void)n_in; (void)out_size;
    const float* x   = (const float*)d_in[0];
    const void*  ei  = d_in[1];
    const float* ea  = (const float*)d_in[2];
    const float* td  = (const float*)d_in[3];
    const float* Wl1 = (const float*)d_in[4];
    const float* bl1 = (const float*)d_in[5];
    const float* Wr1 = (const float*)d_in[6];
    const float* Wl2 = (const float*)d_in[7];
    const float* bl2 = (const float*)d_in[8];
    const float* Wr2 = (const float*)d_in[9];
    const float* Wl3 = (const float*)d_in[10];
    const float* bl3 = (const float*)d_in[11];
    const float* Wr3 = (const float*)d_in[12];
    const float* W1  = (const float*)d_in[13];
    const float* b1  = (const float*)d_in[14];
    const float* W2  = (const float*)d_in[15];
    const float* b2  = (const float*)d_in[16];
    const float* W3  = (const float*)d_in[17];
    const float* b3  = (const float*)d_in[18];
    float* out = (float*)d_out;

    const int DYNSMEM = 4 * 128 * ZSTR * 2;   // 73728 B
    cudaFuncSetAttribute(k_edge_mma, cudaFuncAttributeMaxDynamicSharedMemorySize, DYNSMEM);

    // CSR build
    k_detect<<<1, 1>>>((const int*)ei);
    k_zero_deg<<<(NN + 255) / 256, 256>>>();
    k_prep<<<(NE + 255) / 256, 256>>>(ei);
    k_scan<<<1, 1024>>>();
    k_fill<<<(NE + 255) / 256, 256>>>();

    // W2^T bf16 hi/lo images
    k_w2prep<<<(128 * 256 + 255) / 256, 256>>>(W2);

    dim3 ggrid(2, (NN + 127) / 128);

    // layer 1 (din=3)
    k_aggr<<<NN, 32>>>(x, -1, 3);
    k_layer1<<<NN, 256>>>(x, Wl1, bl1, Wr1);

    // layer 2
    k_aggr<<<NN, 256>>>(nullptr, 0, 256);
    k_sgemm<<<ggrid, 256>>>(2, Wl2, 0, Wr2, bl2, 1, NN, 1);

    // layer 3
    k_aggr<<<NN, 256>>>(nullptr, 1, 256);
    k_sgemm<<<ggrid, 256>>>(2, Wl3, 1, Wr3, bl3, 0, NN, 1);

    // edge-MLP layer-1 factorization
    k_sgemm<<<ggrid, 256>>>(0, W1,             -1, nullptr, nullptr, 3, NN, 0);
    k_sgemm<<<ggrid, 256>>>(0, W1 + 256 * 256, -1, nullptr, nullptr, 4, NN, 0);

    // mma.sync fused edge MLP
    k_edge_mma<<<(NE + 127) / 128, 256, DYNSMEM>>>(ea, W1, b1, b2, W3, b3, td, out);
}